// round 4
// baseline (speedup 1.0000x reference)
#include <cuda_runtime.h>
#include <cuda_bf16.h>
#include <math.h>

#define T_TOK 4096
#define HDIM  1024
#define IDIM  2816
#define NE    7

#define BM 128
#define BN 64
#define BK 16

// Scratch: y1 intermediate per path (z=0 shared, z=1..7 experts), compacted rows.
__device__ float g_y1[8ull * T_TOK * IDIM];
__device__ int   g_cnt[NE];
__device__ int   g_tok[NE * T_TOK];
__device__ float g_wt [NE * T_TOK];

__global__ void init_counts_kernel() {
    if (threadIdx.x < NE) g_cnt[threadIdx.x] = 0;
}

// One warp per token: logits = x @ Wr + b, sigmoid, top-2, renormalize, append.
__global__ void router_kernel(const float* __restrict__ x,
                              const float* __restrict__ wr,
                              const float* __restrict__ bias) {
    int warp = (blockIdx.x * blockDim.x + threadIdx.x) >> 5;
    int lane = threadIdx.x & 31;
    if (warp >= T_TOK) return;
    const float* xr = x + (size_t)warp * HDIM;
    float acc[NE];
#pragma unroll
    for (int e = 0; e < NE; e++) acc[e] = 0.f;
    for (int h = lane; h < HDIM; h += 32) {
        float xv = xr[h];
#pragma unroll
        for (int e = 0; e < NE; e++) acc[e] += xv * wr[h * NE + e];
    }
#pragma unroll
    for (int e = 0; e < NE; e++) {
#pragma unroll
        for (int o = 16; o > 0; o >>= 1)
            acc[e] += __shfl_xor_sync(0xffffffffu, acc[e], o);
    }
    if (lane == 0) {
        float p[NE];
#pragma unroll
        for (int e = 0; e < NE; e++)
            p[e] = 1.f / (1.f + expf(-(acc[e] + bias[e])));
        int i0 = 0; float s0 = p[0];
#pragma unroll
        for (int e = 1; e < NE; e++) if (p[e] > s0) { s0 = p[e]; i0 = e; }
        int i1 = -1; float s1 = -1.f;
#pragma unroll
        for (int e = 0; e < NE; e++) if (e != i0 && p[e] > s1) { s1 = p[e]; i1 = e; }
        float inv = 1.f / (s0 + s1);
        int p0 = atomicAdd(&g_cnt[i0], 1);
        g_tok[i0 * T_TOK + p0] = warp;
        g_wt [i0 * T_TOK + p0] = s0 * inv;
        int p1 = atomicAdd(&g_cnt[i1], 1);
        g_tok[i1 * T_TOK + p1] = warp;
        g_wt [i1 * T_TOK + p1] = s1 * inv;
    }
}

// Fused gate+up GEMM + SiLU combine.  z=0: shared expert (all tokens),
// z=1..7: routed expert z-1 (gathered rows from g_tok).  Writes compacted
// rows into g_y1[z].
__global__ __launch_bounds__(256, 2)
void gemm1_kernel(const float* __restrict__ x,
                  const float* __restrict__ sg,
                  const float* __restrict__ su,
                  const float* __restrict__ rg,
                  const float* __restrict__ ru) {
    int z = blockIdx.z;
    const float *Bg, *Bu;
    int nrows;
    const int* idx;
    float* Cp = g_y1 + (size_t)z * T_TOK * IDIM;
    if (z == 0) {
        Bg = sg; Bu = su; nrows = T_TOK; idx = nullptr;
    } else {
        int e = z - 1;
        Bg = rg + (size_t)e * HDIM * IDIM;
        Bu = ru + (size_t)e * HDIM * IDIM;
        nrows = g_cnt[e];
        idx = g_tok + e * T_TOK;
    }
    int m0 = blockIdx.y * BM;
    if (m0 >= nrows) return;
    int n0 = blockIdx.x * BN;

    __shared__ float As[BK][BM];
    __shared__ float Bs[2][BK][BN];

    int tid = threadIdx.x;          // 256 threads
    int tx = tid & 15, ty = tid >> 4;

    // Resolve gathered A row indices once.
    int arow[2];
#pragma unroll
    for (int l = 0; l < 2; l++) {
        int m  = (tid + l * 256) >> 2;
        int gm = m0 + m;
        if (idx) arow[l] = (gm < nrows) ? idx[gm] : idx[0];
        else     arow[l] = gm;
    }

    float acc0[8][4] = {}, acc1[8][4] = {};

    for (int k0 = 0; k0 < HDIM; k0 += BK) {
        // A tile (transposed into smem: As[k][m])
#pragma unroll
        for (int l = 0; l < 2; l++) {
            int e4 = tid + l * 256;
            int m = e4 >> 2, kq = e4 & 3;
            float4 v = *(const float4*)(x + (size_t)arow[l] * HDIM + k0 + kq * 4);
            As[kq * 4 + 0][m] = v.x;
            As[kq * 4 + 1][m] = v.y;
            As[kq * 4 + 2][m] = v.z;
            As[kq * 4 + 3][m] = v.w;
        }
        // B tiles (gate and up), row-major [k][n]
        {
            int k = tid >> 4, nq = tid & 15;
            float4 v1 = *(const float4*)(Bg + (size_t)(k0 + k) * IDIM + n0 + nq * 4);
            *(float4*)&Bs[0][k][nq * 4] = v1;
            float4 v2 = *(const float4*)(Bu + (size_t)(k0 + k) * IDIM + n0 + nq * 4);
            *(float4*)&Bs[1][k][nq * 4] = v2;
        }
        __syncthreads();
#pragma unroll
        for (int k = 0; k < BK; k++) {
            float a[8], bg[4], bu[4];
#pragma unroll
            for (int i = 0; i < 8; i++) a[i] = As[k][ty * 8 + i];
#pragma unroll
            for (int j = 0; j < 4; j++) {
                bg[j] = Bs[0][k][tx * 4 + j];
                bu[j] = Bs[1][k][tx * 4 + j];
            }
#pragma unroll
            for (int i = 0; i < 8; i++)
#pragma unroll
                for (int j = 0; j < 4; j++) {
                    acc0[i][j] += a[i] * bg[j];
                    acc1[i][j] += a[i] * bu[j];
                }
        }
        __syncthreads();
    }
    // Epilogue: y1 = silu(gate) * up
#pragma unroll
    for (int i = 0; i < 8; i++) {
        int m = m0 + ty * 8 + i;
        if (m < nrows) {
            float* crow = Cp + (size_t)m * IDIM + n0 + tx * 4;
#pragma unroll
            for (int j = 0; j < 4; j++) {
                float g = acc0[i][j];
                crow[j] = g / (1.f + expf(-g)) * acc1[i][j];
            }
        }
    }
}

// Down-projection for the shared expert: out = y1_shared @ Down (direct store,
// covers every element of d_out).
__global__ __launch_bounds__(256, 2)
void gemm2_shared_kernel(const float* __restrict__ sd,
                         float* __restrict__ out) {
    const float* Ap = g_y1;   // z = 0
    int m0 = blockIdx.y * BM;
    int n0 = blockIdx.x * BN;

    __shared__ float As[BK][BM];
    __shared__ float Bs[BK][BN];

    int tid = threadIdx.x;
    int tx = tid & 15, ty = tid >> 4;
    float acc[8][4] = {};

    for (int k0 = 0; k0 < IDIM; k0 += BK) {
#pragma unroll
        for (int l = 0; l < 2; l++) {
            int e4 = tid + l * 256;
            int m = e4 >> 2, kq = e4 & 3;
            float4 v = *(const float4*)(Ap + (size_t)(m0 + m) * IDIM + k0 + kq * 4);
            As[kq * 4 + 0][m] = v.x;
            As[kq * 4 + 1][m] = v.y;
            As[kq * 4 + 2][m] = v.z;
            As[kq * 4 + 3][m] = v.w;
        }
        {
            int k = tid >> 4, nq = tid & 15;
            float4 v = *(const float4*)(sd + (size_t)(k0 + k) * HDIM + n0 + nq * 4);
            *(float4*)&Bs[k][nq * 4] = v;
        }
        __syncthreads();
#pragma unroll
        for (int k = 0; k < BK; k++) {
            float a[8], b[4];
#pragma unroll
            for (int i = 0; i < 8; i++) a[i] = As[k][ty * 8 + i];
#pragma unroll
            for (int j = 0; j < 4; j++) b[j] = Bs[k][tx * 4 + j];
#pragma unroll
            for (int i = 0; i < 8; i++)
#pragma unroll
                for (int j = 0; j < 4; j++) acc[i][j] += a[i] * b[j];
        }
        __syncthreads();
    }
#pragma unroll
    for (int i = 0; i < 8; i++) {
        int m = m0 + ty * 8 + i;
        float* crow = out + (size_t)m * HDIM + n0 + tx * 4;
#pragma unroll
        for (int j = 0; j < 4; j++) crow[j] = acc[i][j];
    }
}

// Down-projection for routed experts: out[tok] += w * (y1_e @ Down_e),
// z = expert index, scatter via atomicAdd.
__global__ __launch_bounds__(256, 2)
void gemm2_routed_kernel(const float* __restrict__ rd,
                         float* __restrict__ out) {
    int e = blockIdx.z;
    int nrows = g_cnt[e];
    int m0 = blockIdx.y * BM;
    if (m0 >= nrows) return;
    int n0 = blockIdx.x * BN;
    const float* Ap = g_y1 + (size_t)(e + 1) * T_TOK * IDIM;
    const float* Bp = rd + (size_t)e * IDIM * HDIM;
    const int*   tk = g_tok + e * T_TOK;
    const float* wt = g_wt  + e * T_TOK;

    __shared__ float As[BK][BM];
    __shared__ float Bs[BK][BN];

    int tid = threadIdx.x;
    int tx = tid & 15, ty = tid >> 4;
    float acc[8][4] = {};

    int arow[2];
#pragma unroll
    for (int l = 0; l < 2; l++) {
        int m  = (tid + l * 256) >> 2;
        int gm = m0 + m;
        arow[l] = (gm < nrows) ? gm : (nrows - 1);
    }

    for (int k0 = 0; k0 < IDIM; k0 += BK) {
#pragma unroll
        for (int l = 0; l < 2; l++) {
            int e4 = tid + l * 256;
            int m = e4 >> 2, kq = e4 & 3;
            float4 v = *(const float4*)(Ap + (size_t)arow[l] * IDIM + k0 + kq * 4);
            As[kq * 4 + 0][m] = v.x;
            As[kq * 4 + 1][m] = v.y;
            As[kq * 4 + 2][m] = v.z;
            As[kq * 4 + 3][m] = v.w;
        }
        {
            int k = tid >> 4, nq = tid & 15;
            float4 v = *(const float4*)(Bp + (size_t)(k0 + k) * HDIM + n0 + nq * 4);
            *(float4*)&Bs[k][nq * 4] = v;
        }
        __syncthreads();
#pragma unroll
        for (int k = 0; k < BK; k++) {
            float a[8], b[4];
#pragma unroll
            for (int i = 0; i < 8; i++) a[i] = As[k][ty * 8 + i];
#pragma unroll
            for (int j = 0; j < 4; j++) b[j] = Bs[k][tx * 4 + j];
#pragma unroll
            for (int i = 0; i < 8; i++)
#pragma unroll
                for (int j = 0; j < 4; j++) acc[i][j] += a[i] * b[j];
        }
        __syncthreads();
    }
#pragma unroll
    for (int i = 0; i < 8; i++) {
        int m = m0 + ty * 8 + i;
        if (m < nrows) {
            int   t = tk[m];
            float w = wt[m];
            float* crow = out + (size_t)t * HDIM + n0 + tx * 4;
#pragma unroll
            for (int j = 0; j < 4; j++)
                atomicAdd(&crow[j], w * acc[i][j]);
        }
    }
}

extern "C" void kernel_launch(void* const* d_in, const int* in_sizes, int n_in,
                              void* d_out, int out_size) {
    const float* x    = (const float*)d_in[0];
    const float* wr   = (const float*)d_in[1];
    const float* bias = (const float*)d_in[2];
    const float* sg   = (const float*)d_in[3];
    const float* su   = (const float*)d_in[4];
    const float* sd   = (const float*)d_in[5];
    const float* rg   = (const float*)d_in[6];
    const float* ru   = (const float*)d_in[7];
    const float* rd   = (const float*)d_in[8];
    float* out = (float*)d_out;

    init_counts_kernel<<<1, 32>>>();
    router_kernel<<<T_TOK / 4, 128>>>(x, wr, bias);

    dim3 g1(IDIM / BN, T_TOK / BM, 8);
    gemm1_kernel<<<g1, 256>>>(x, sg, su, rg, ru);

    dim3 g2s(HDIM / BN, T_TOK / BM, 1);
    gemm2_shared_kernel<<<g2s, 256>>>(sd, out);

    dim3 g2r(HDIM / BN, T_TOK / BM, NE);
    gemm2_routed_kernel<<<g2r, 256>>>(rd, out);
}

// round 6
// speedup vs baseline: 2.0671x; 2.0671x over previous
#include <cuda_runtime.h>
#include <cuda_bf16.h>
#include <math.h>
#include <stdint.h>

#define T_TOK 4096
#define HDIM  1024
#define IDIM  2816
#define NE    7
#define BK    32

// smem row pitch: 40 bf16 = 80 bytes -> conflict-free ldmatrix with 8-row strides
#define PITCHB 80

// per-stage segment offsets (bytes): 128 rows each of A(hi,lo) and B(hi,lo)
#define S_AHI 0
#define S_ALO 10240
#define S_BHI 20480
#define S_BLO 30720
#define STAGE 40960
#define SM_G1 (2*STAGE + 512)
#define SM_G2 (2*STAGE)

// ---------------- device scratch ----------------
__device__ __nv_bfloat16 g_xhi[(size_t)T_TOK*HDIM];
__device__ __nv_bfloat16 g_xlo[(size_t)T_TOK*HDIM];
__device__ __nv_bfloat16 g_g1h[8ull*IDIM*HDIM], g_g1l[8ull*IDIM*HDIM];
__device__ __nv_bfloat16 g_u1h[8ull*IDIM*HDIM], g_u1l[8ull*IDIM*HDIM];
__device__ __nv_bfloat16 g_d2h[8ull*HDIM*IDIM], g_d2l[8ull*HDIM*IDIM];
__device__ __nv_bfloat16 g_y1h[8ull*T_TOK*IDIM], g_y1l[8ull*T_TOK*IDIM];
__device__ int   g_cnt[NE];
__device__ int   g_tok[NE * T_TOK];
__device__ float g_wt [NE * T_TOK];

// ---------------- helpers ----------------
__device__ __forceinline__ uint32_t smem_u32(const void* p) {
    uint32_t a;
    asm("{ .reg .u64 t; cvta.to.shared.u64 t, %1; cvt.u32.u64 %0, t; }" : "=r"(a) : "l"(p));
    return a;
}
__device__ __forceinline__ void ldmx4(uint32_t* r, uint32_t addr) {
    asm volatile("ldmatrix.sync.aligned.m8n8.x4.shared.b16 {%0,%1,%2,%3}, [%4];"
        : "=r"(r[0]), "=r"(r[1]), "=r"(r[2]), "=r"(r[3]) : "r"(addr));
}
__device__ __forceinline__ void mma16816(float* d, const uint32_t* a, const uint32_t* b) {
    asm volatile("mma.sync.aligned.m16n8k16.row.col.f32.bf16.bf16.f32 "
        "{%0,%1,%2,%3}, {%4,%5,%6,%7}, {%8,%9}, {%0,%1,%2,%3};"
        : "+f"(d[0]), "+f"(d[1]), "+f"(d[2]), "+f"(d[3])
        : "r"(a[0]), "r"(a[1]), "r"(a[2]), "r"(a[3]), "r"(b[0]), "r"(b[1]));
}
__device__ __forceinline__ void cp16(uint32_t saddr, const void* gaddr) {
    asm volatile("cp.async.cg.shared.global [%0], [%1], 16;" :: "r"(saddr), "l"(gaddr));
}
__device__ __forceinline__ void cp_commit() { asm volatile("cp.async.commit_group;" ::: "memory"); }
template<int N> __device__ __forceinline__ void cp_wait() {
    asm volatile("cp.async.wait_group %0;" :: "n"(N) : "memory");
}
__device__ __forceinline__ uint32_t pack_hi(float a, float b) {
    __nv_bfloat162 h = __floats2bfloat162_rn(a, b);
    return *(uint32_t*)&h;
}

// ---------------- small kernels ----------------
__global__ void init_counts_kernel() {
    if (threadIdx.x < NE) g_cnt[threadIdx.x] = 0;
}

__global__ void router_kernel(const float* __restrict__ x,
                              const float* __restrict__ wr,
                              const float* __restrict__ bias) {
    int warp = (blockIdx.x * blockDim.x + threadIdx.x) >> 5;
    int lane = threadIdx.x & 31;
    if (warp >= T_TOK) return;
    const float* xr = x + (size_t)warp * HDIM;
    float acc[NE];
#pragma unroll
    for (int e = 0; e < NE; e++) acc[e] = 0.f;
    for (int h = lane; h < HDIM; h += 32) {
        float xv = xr[h];
#pragma unroll
        for (int e = 0; e < NE; e++) acc[e] += xv * wr[h * NE + e];
    }
#pragma unroll
    for (int e = 0; e < NE; e++) {
#pragma unroll
        for (int o = 16; o > 0; o >>= 1)
            acc[e] += __shfl_xor_sync(0xffffffffu, acc[e], o);
    }
    if (lane == 0) {
        float p[NE];
#pragma unroll
        for (int e = 0; e < NE; e++)
            p[e] = 1.f / (1.f + expf(-(acc[e] + bias[e])));
        int i0 = 0; float s0 = p[0];
#pragma unroll
        for (int e = 1; e < NE; e++) if (p[e] > s0) { s0 = p[e]; i0 = e; }
        int i1 = -1; float s1 = -1.f;
#pragma unroll
        for (int e = 0; e < NE; e++) if (e != i0 && p[e] > s1) { s1 = p[e]; i1 = e; }
        float inv = 1.f / (s0 + s1);
        int p0 = atomicAdd(&g_cnt[i0], 1);
        g_tok[i0 * T_TOK + p0] = warp;
        g_wt [i0 * T_TOK + p0] = s0 * inv;
        int p1 = atomicAdd(&g_cnt[i1], 1);
        g_tok[i1 * T_TOK + p1] = warp;
        g_wt [i1 * T_TOK + p1] = s1 * inv;
    }
}

__global__ void convx_kernel(const float* __restrict__ x) {
    size_t i = ((size_t)blockIdx.x * 256 + threadIdx.x) * 4;
    float4 v = *(const float4*)(x + i);
    float vv[4] = {v.x, v.y, v.z, v.w};
    unsigned short h[4], l[4];
#pragma unroll
    for (int j = 0; j < 4; j++) {
        __nv_bfloat16 hb = __float2bfloat16(vv[j]);
        float lf = vv[j] - __bfloat162float(hb);
        h[j] = __bfloat16_as_ushort(hb);
        l[j] = __bfloat16_as_ushort(__float2bfloat16(lf));
    }
    uint2 uh, ul;
    uh.x = (uint32_t)h[0] | ((uint32_t)h[1] << 16);
    uh.y = (uint32_t)h[2] | ((uint32_t)h[3] << 16);
    ul.x = (uint32_t)l[0] | ((uint32_t)l[1] << 16);
    ul.y = (uint32_t)l[2] | ((uint32_t)l[3] << 16);
    *(uint2*)(g_xhi + i) = uh;
    *(uint2*)(g_xlo + i) = ul;
}

// transpose-convert: src fp32 [K][N] row-major -> dst bf16 hi/lo [N][K]
__device__ __forceinline__ void transpose_cv(const float* __restrict__ src,
                                             __nv_bfloat16* dh, __nv_bfloat16* dl,
                                             int K, int N) {
    __shared__ float t[32][33];
    int tx = threadIdx.x, ty = threadIdx.y;
    int n0 = blockIdx.x * 32, k0 = blockIdx.y * 32;
#pragma unroll
    for (int i = 0; i < 4; i++)
        t[ty + i * 8][tx] = src[(size_t)(k0 + ty + i * 8) * N + n0 + tx];
    __syncthreads();
#pragma unroll
    for (int i = 0; i < 4; i++) {
        int n = n0 + ty + i * 8, k = k0 + tx;
        float v = t[tx][ty + i * 8];
        __nv_bfloat16 h = __float2bfloat16(v);
        float lf = v - __bfloat162float(h);
        dh[(size_t)n * K + k] = h;
        dl[(size_t)n * K + k] = __float2bfloat16(lf);
    }
}

__global__ void convT1_kernel(const float* __restrict__ sg, const float* __restrict__ su,
                              const float* __restrict__ rg, const float* __restrict__ ru) {
    int z = blockIdx.z;
    const float* src; __nv_bfloat16 *dh, *dl; size_t mo;
    if (z == 0)       { src = sg; dh = g_g1h; dl = g_g1l; mo = 0; }
    else if (z == 1)  { src = su; dh = g_u1h; dl = g_u1l; mo = 0; }
    else if (z < 9)   { int e = z - 2; src = rg + (size_t)e * HDIM * IDIM; dh = g_g1h; dl = g_g1l; mo = (size_t)(e + 1) * IDIM * HDIM; }
    else              { int e = z - 9; src = ru + (size_t)e * HDIM * IDIM; dh = g_u1h; dl = g_u1l; mo = (size_t)(e + 1) * IDIM * HDIM; }
    transpose_cv(src, dh + mo, dl + mo, HDIM, IDIM);
}

__global__ void convT2_kernel(const float* __restrict__ sd, const float* __restrict__ rd) {
    int z = blockIdx.z;
    const float* src = (z == 0) ? sd : rd + (size_t)(z - 1) * IDIM * HDIM;
    size_t mo = (size_t)z * HDIM * IDIM;
    transpose_cv(src, g_d2h + mo, g_d2l + mo, IDIM, HDIM);
}

// ---------------- gemm1: y1 = silu(x@G) * (x@U)  (mma.sync bf16 hi/lo) ----------------
// CTA tile: 128 m x 64 n (both gate and up).  8 warps, warp tile 32m x 32n.
__global__ __launch_bounds__(256, 1)
void gemm1_kernel() {
    extern __shared__ char smem[];
    int tid = threadIdx.x;
    int z = blockIdx.z;
    int nrows; const int* idx;
    if (z == 0) { nrows = T_TOK; idx = nullptr; }
    else        { nrows = g_cnt[z - 1]; idx = g_tok + (z - 1) * T_TOK; }
    int m0 = blockIdx.y * 128;
    if (m0 >= nrows) return;
    int n0 = blockIdx.x * 64;

    const __nv_bfloat16* gH = g_g1h + (size_t)z * IDIM * HDIM;
    const __nv_bfloat16* gL = g_g1l + (size_t)z * IDIM * HDIM;
    const __nv_bfloat16* uH = g_u1h + (size_t)z * IDIM * HDIM;
    const __nv_bfloat16* uL = g_u1l + (size_t)z * IDIM * HDIM;

    int* arow_s = (int*)(smem + 2 * STAGE);
    if (tid < 128) {
        int gm = m0 + tid;
        arow_s[tid] = idx ? ((gm < nrows) ? idx[gm] : idx[0]) : gm;
    }
    __syncthreads();
    uint32_t sb = smem_u32(smem);

    auto load_stage = [&](int s, int k0) {
        uint32_t base = sb + s * STAGE;
#pragma unroll
        for (int i = 0; i < 8; i++) {
            int cid = tid + i * 256;
            int seg = cid >> 9;            // 0 Ahi, 1 Alo, 2 Bhi, 3 Blo
            int w2  = cid & 511;
            int row = w2 >> 2, c = w2 & 3;
            const __nv_bfloat16* src;
            if (seg < 2) {
                src = ((seg == 0) ? g_xhi : g_xlo) + (size_t)arow_s[row] * HDIM + k0 + c * 8;
            } else {
                int isHi = (seg == 2);
                const __nv_bfloat16* bp;
                if (row < 64) bp = (isHi ? gH : gL) + (size_t)(n0 + row) * HDIM;
                else          bp = (isHi ? uH : uL) + (size_t)(n0 + row - 64) * HDIM;
                src = bp + k0 + c * 8;
            }
            cp16(base + seg * 10240 + row * PITCHB + c * 16, src);
        }
    };

    int l = tid & 31, w = tid >> 5;
    int wm = w & 3, wn = w >> 2;         // warp grid 4m x 2n
    int mW = wm * 32, nW = wn * 32;
    uint32_t aRow = (uint32_t)(l & 15);
    uint32_t aKb  = (uint32_t)(((l >> 4) & 1) * 16);
    uint32_t bRow = (uint32_t)((l & 7) + ((l >> 4) & 1) * 8);
    uint32_t bKb  = (uint32_t)(((l >> 3) & 1) * 16);

    float Cg[2][4][4] = {}, Cu[2][4][4] = {};

    load_stage(0, 0);
    cp_commit();
    const int NIT = HDIM / BK;   // 32
    for (int it = 0; it < NIT; it++) {
        if (it + 1 < NIT) { load_stage((it + 1) & 1, (it + 1) * BK); cp_commit(); cp_wait<1>(); }
        else              { cp_wait<0>(); }
        __syncthreads();
        uint32_t base = sb + (it & 1) * STAGE;
#pragma unroll
        for (int ks = 0; ks < 2; ks++) {
            int kb = ks * 32;   // bytes (16 elts * 2B)
            uint32_t ah[2][4], al[2][4];
#pragma unroll
            for (int mt = 0; mt < 2; mt++) {
                uint32_t r = base + S_AHI + (mW + mt * 16 + aRow) * PITCHB + kb + aKb;
                ldmx4(ah[mt], r);
                ldmx4(al[mt], r + (S_ALO - S_AHI));
            }
            uint32_t bgh[2][4], bgl[2][4], buh[2][4], bul[2][4];
#pragma unroll
            for (int p = 0; p < 2; p++) {
                uint32_t rg2 = base + S_BHI + (nW + p * 16 + bRow) * PITCHB + kb + bKb;
                ldmx4(bgh[p], rg2);
                ldmx4(bgl[p], rg2 + (S_BLO - S_BHI));
                ldmx4(buh[p], rg2 + 64 * PITCHB);
                ldmx4(bul[p], rg2 + 64 * PITCHB + (S_BLO - S_BHI));
            }
#pragma unroll
            for (int mt = 0; mt < 2; mt++)
#pragma unroll
                for (int nt = 0; nt < 4; nt++) {
                    const uint32_t* bGH = &bgh[nt >> 1][(nt & 1) * 2];
                    const uint32_t* bGL = &bgl[nt >> 1][(nt & 1) * 2];
                    const uint32_t* bUH = &buh[nt >> 1][(nt & 1) * 2];
                    const uint32_t* bUL = &bul[nt >> 1][(nt & 1) * 2];
                    mma16816(Cg[mt][nt], ah[mt], bGH);
                    mma16816(Cg[mt][nt], ah[mt], bGL);
                    mma16816(Cg[mt][nt], al[mt], bGH);
                    mma16816(Cu[mt][nt], ah[mt], bUH);
                    mma16816(Cu[mt][nt], ah[mt], bUL);
                    mma16816(Cu[mt][nt], al[mt], bUH);
                }
        }
        __syncthreads();
    }

    // epilogue: y = silu(g)*u -> bf16 hi/lo, compacted rows
    size_t zb = (size_t)z * T_TOK;
#pragma unroll
    for (int mt = 0; mt < 2; mt++)
#pragma unroll
        for (int nt = 0; nt < 4; nt++) {
            int mrow = m0 + mW + mt * 16 + (l >> 2);
            int ncol = n0 + nW + nt * 8 + (l & 3) * 2;
#pragma unroll
            for (int h = 0; h < 2; h++) {
                int m = mrow + h * 8;
                if (m < nrows) {
                    float gg0 = Cg[mt][nt][2 * h],     uu0 = Cu[mt][nt][2 * h];
                    float gg1 = Cg[mt][nt][2 * h + 1], uu1 = Cu[mt][nt][2 * h + 1];
                    float y0 = gg0 / (1.f + __expf(-gg0)) * uu0;
                    float y1 = gg1 / (1.f + __expf(-gg1)) * uu1;
                    uint32_t hp = pack_hi(y0, y1);
                    __nv_bfloat162 hv = *(__nv_bfloat162*)&hp;
                    float l0 = y0 - __bfloat162float(hv.x);
                    float l1 = y1 - __bfloat162float(hv.y);
                    uint32_t lp = pack_hi(l0, l1);
                    size_t off = (zb + m) * IDIM + ncol;
                    *(uint32_t*)(g_y1h + off) = hp;
                    *(uint32_t*)(g_y1l + off) = lp;
                }
            }
        }
}

// ---------------- gemm2: out = y1 @ D ----------------
// CTA tile: 128 m x 128 n.  8 warps, warp tile 64m x 32n (grid 2m x 4n).
__global__ __launch_bounds__(256, 1)
void gemm2_kernel(float* __restrict__ out, int routed) {
    extern __shared__ char smem[];
    int tid = threadIdx.x;
    int z = routed ? (blockIdx.z + 1) : 0;
    int nrows = routed ? g_cnt[z - 1] : T_TOK;
    int m0 = blockIdx.y * 128;
    if (m0 >= nrows) return;
    int n0 = blockIdx.x * 128;

    const __nv_bfloat16* aH = g_y1h + (size_t)z * T_TOK * IDIM;
    const __nv_bfloat16* aL = g_y1l + (size_t)z * T_TOK * IDIM;
    const __nv_bfloat16* bH = g_d2h + (size_t)z * HDIM * IDIM;
    const __nv_bfloat16* bL = g_d2l + (size_t)z * HDIM * IDIM;

    uint32_t sb = smem_u32(smem);

    auto load_stage = [&](int s, int k0) {
        uint32_t base = sb + s * STAGE;
#pragma unroll
        for (int i = 0; i < 8; i++) {
            int cid = tid + i * 256;
            int seg = cid >> 9;
            int w2  = cid & 511;
            int row = w2 >> 2, c = w2 & 3;
            const __nv_bfloat16* src;
            if (seg < 2) {
                int r = m0 + row; if (r >= nrows) r = nrows - 1;
                src = ((seg == 0) ? aH : aL) + (size_t)r * IDIM + k0 + c * 8;
            } else {
                src = ((seg == 2) ? bH : bL) + (size_t)(n0 + row) * IDIM + k0 + c * 8;
            }
            cp16(base + seg * 10240 + row * PITCHB + c * 16, src);
        }
    };

    int l = tid & 31, w = tid >> 5;
    int wm = w & 1, wn = w >> 1;         // warp grid 2m x 4n
    int mW = wm * 64, nW = wn * 32;
    uint32_t aRow = (uint32_t)(l & 15);
    uint32_t aKb  = (uint32_t)(((l >> 4) & 1) * 16);
    uint32_t bRow = (uint32_t)((l & 7) + ((l >> 4) & 1) * 8);
    uint32_t bKb  = (uint32_t)(((l >> 3) & 1) * 16);

    float C[4][4][4] = {};

    load_stage(0, 0);
    cp_commit();
    const int NIT = IDIM / BK;   // 88
    for (int it = 0; it < NIT; it++) {
        if (it + 1 < NIT) { load_stage((it + 1) & 1, (it + 1) * BK); cp_commit(); cp_wait<1>(); }
        else              { cp_wait<0>(); }
        __syncthreads();
        uint32_t base = sb + (it & 1) * STAGE;
#pragma unroll
        for (int ks = 0; ks < 2; ks++) {
            int kb = ks * 32;
            uint32_t ah[4][4], al[4][4];
#pragma unroll
            for (int mt = 0; mt < 4; mt++) {
                uint32_t r = base + S_AHI + (mW + mt * 16 + aRow) * PITCHB + kb + aKb;
                ldmx4(ah[mt], r);
                ldmx4(al[mt], r + (S_ALO - S_AHI));
            }
            uint32_t bh[2][4], bl[2][4];
#pragma unroll
            for (int p = 0; p < 2; p++) {
                uint32_t r = base + S_BHI + (nW + p * 16 + bRow) * PITCHB + kb + bKb;
                ldmx4(bh[p], r);
                ldmx4(bl[p], r + (S_BLO - S_BHI));
            }
#pragma unroll
            for (int mt = 0; mt < 4; mt++)
#pragma unroll
                for (int nt = 0; nt < 4; nt++) {
                    const uint32_t* bH2 = &bh[nt >> 1][(nt & 1) * 2];
                    const uint32_t* bL2 = &bl[nt >> 1][(nt & 1) * 2];
                    mma16816(C[mt][nt], ah[mt], bH2);
                    mma16816(C[mt][nt], ah[mt], bL2);
                    mma16816(C[mt][nt], al[mt], bH2);
                }
        }
        __syncthreads();
    }

#pragma unroll
    for (int mt = 0; mt < 4; mt++)
#pragma unroll
        for (int nt = 0; nt < 4; nt++) {
            int mrow = m0 + mW + mt * 16 + (l >> 2);
            int ncol = n0 + nW + nt * 8 + (l & 3) * 2;
#pragma unroll
            for (int h = 0; h < 2; h++) {
                int m = mrow + h * 8;
                if (!routed) {
                    float2 v = make_float2(C[mt][nt][2 * h], C[mt][nt][2 * h + 1]);
                    *(float2*)(out + (size_t)m * HDIM + ncol) = v;
                } else if (m < nrows) {
                    int   tok = g_tok[(z - 1) * T_TOK + m];
                    float wgt = g_wt [(z - 1) * T_TOK + m];
                    float* dst = out + (size_t)tok * HDIM + ncol;
                    atomicAdd(dst,     wgt * C[mt][nt][2 * h]);
                    atomicAdd(dst + 1, wgt * C[mt][nt][2 * h + 1]);
                }
            }
        }
}

// ---------------- launch ----------------
extern "C" void kernel_launch(void* const* d_in, const int* in_sizes, int n_in,
                              void* d_out, int out_size) {
    const float* x    = (const float*)d_in[0];
    const float* wr   = (const float*)d_in[1];
    const float* bias = (const float*)d_in[2];
    const float* sg   = (const float*)d_in[3];
    const float* su   = (const float*)d_in[4];
    const float* sd   = (const float*)d_in[5];
    const float* rg   = (const float*)d_in[6];
    const float* ru   = (const float*)d_in[7];
    const float* rd   = (const float*)d_in[8];
    float* out = (float*)d_out;

    cudaFuncSetAttribute(gemm1_kernel, cudaFuncAttributeMaxDynamicSharedMemorySize, SM_G1);
    cudaFuncSetAttribute(gemm2_kernel, cudaFuncAttributeMaxDynamicSharedMemorySize, SM_G2);

    init_counts_kernel<<<1, 32>>>();
    router_kernel<<<T_TOK / 4, 128>>>(x, wr, bias);
    convx_kernel<<<(T_TOK * HDIM) / 1024, 256>>>(x);
    convT1_kernel<<<dim3(IDIM / 32, HDIM / 32, 16), dim3(32, 8)>>>(sg, su, rg, ru);
    convT2_kernel<<<dim3(HDIM / 32, IDIM / 32, 8), dim3(32, 8)>>>(sd, rd);

    gemm1_kernel<<<dim3(IDIM / 64, T_TOK / 128, 8), 256, SM_G1>>>();
    gemm2_kernel<<<dim3(HDIM / 128, T_TOK / 128, 1), 256, SM_G2>>>(out, 0);
    gemm2_kernel<<<dim3(HDIM / 128, T_TOK / 128, NE), 256, SM_G2>>>(out, 1);
}

// round 9
// speedup vs baseline: 3.2485x; 1.5715x over previous
#include <cuda_runtime.h>
#include <cuda_fp16.h>
#include <math.h>
#include <stdint.h>

#define T_TOK 4096
#define HDIM  1024
#define IDIM  2816
#define NE    7
#define BK    32

// smem row pitch: 40 halves = 80 bytes -> conflict-free ldmatrix with 8-row strides
#define PITCHB 80

// per-stage segment offsets (bytes): 128 rows each of Ahi, Alo, Bhi
#define S_AHI 0
#define S_ALO 10240
#define S_BHI 20480
#define STAGE 30720
#define NST   4
#define SM_G1 (NST*STAGE + 512)
#define SM_G2 (NST*STAGE)

// ---------------- device scratch ----------------
__device__ __half g_xhi[(size_t)T_TOK*HDIM];
__device__ __half g_xlo[(size_t)T_TOK*HDIM];
__device__ __half g_g1h[8ull*IDIM*HDIM];   // gate weights [z][n][k], fp16
__device__ __half g_u1h[8ull*IDIM*HDIM];   // up weights
__device__ __half g_d2h[8ull*HDIM*IDIM];   // down weights [z][n][k]
__device__ __half g_y1h[8ull*T_TOK*IDIM];  // y1 hi
__device__ __half g_y1l[8ull*T_TOK*IDIM];  // y1 lo
__device__ int   g_cnt[NE];
__device__ int   g_tok[NE * T_TOK];
__device__ float g_wt [NE * T_TOK];

// ---------------- helpers ----------------
__device__ __forceinline__ uint32_t smem_u32(const void* p) {
    uint32_t a;
    asm("{ .reg .u64 t; cvta.to.shared.u64 t, %1; cvt.u32.u64 %0, t; }" : "=r"(a) : "l"(p));
    return a;
}
__device__ __forceinline__ void ldmx4(uint32_t* r, uint32_t addr) {
    asm volatile("ldmatrix.sync.aligned.m8n8.x4.shared.b16 {%0,%1,%2,%3}, [%4];"
        : "=r"(r[0]), "=r"(r[1]), "=r"(r[2]), "=r"(r[3]) : "r"(addr));
}
__device__ __forceinline__ void mma16816(float* d, const uint32_t* a, const uint32_t* b) {
    asm volatile("mma.sync.aligned.m16n8k16.row.col.f32.f16.f16.f32 "
        "{%0,%1,%2,%3}, {%4,%5,%6,%7}, {%8,%9}, {%0,%1,%2,%3};"
        : "+f"(d[0]), "+f"(d[1]), "+f"(d[2]), "+f"(d[3])
        : "r"(a[0]), "r"(a[1]), "r"(a[2]), "r"(a[3]), "r"(b[0]), "r"(b[1]));
}
__device__ __forceinline__ void cp16(uint32_t saddr, const void* gaddr) {
    asm volatile("cp.async.cg.shared.global [%0], [%1], 16;" :: "r"(saddr), "l"(gaddr));
}
__device__ __forceinline__ void cp_commit() { asm volatile("cp.async.commit_group;" ::: "memory"); }
template<int N> __device__ __forceinline__ void cp_wait() {
    asm volatile("cp.async.wait_group %0;" :: "n"(N) : "memory");
}
__device__ __forceinline__ uint32_t pack_h2(float a, float b) {
    __half2 h = __floats2half2_rn(a, b);
    return *(uint32_t*)&h;
}

// ---------------- small kernels ----------------
__global__ void init_counts_kernel() {
    if (threadIdx.x < NE) g_cnt[threadIdx.x] = 0;
}

__global__ void router_kernel(const float* __restrict__ x,
                              const float* __restrict__ wr,
                              const float* __restrict__ bias) {
    int warp = (blockIdx.x * blockDim.x + threadIdx.x) >> 5;
    int lane = threadIdx.x & 31;
    if (warp >= T_TOK) return;
    const float* xr = x + (size_t)warp * HDIM;
    float acc[NE];
#pragma unroll
    for (int e = 0; e < NE; e++) acc[e] = 0.f;
    for (int h = lane; h < HDIM; h += 32) {
        float xv = xr[h];
#pragma unroll
        for (int e = 0; e < NE; e++) acc[e] += xv * wr[h * NE + e];
    }
#pragma unroll
    for (int e = 0; e < NE; e++) {
#pragma unroll
        for (int o = 16; o > 0; o >>= 1)
            acc[e] += __shfl_xor_sync(0xffffffffu, acc[e], o);
    }
    if (lane == 0) {
        float p[NE];
#pragma unroll
        for (int e = 0; e < NE; e++)
            p[e] = 1.f / (1.f + expf(-(acc[e] + bias[e])));
        int i0 = 0; float s0 = p[0];
#pragma unroll
        for (int e = 1; e < NE; e++) if (p[e] > s0) { s0 = p[e]; i0 = e; }
        int i1 = -1; float s1 = -1.f;
#pragma unroll
        for (int e = 0; e < NE; e++) if (e != i0 && p[e] > s1) { s1 = p[e]; i1 = e; }
        float inv = 1.f / (s0 + s1);
        int p0 = atomicAdd(&g_cnt[i0], 1);
        g_tok[i0 * T_TOK + p0] = warp;
        g_wt [i0 * T_TOK + p0] = s0 * inv;
        int p1 = atomicAdd(&g_cnt[i1], 1);
        g_tok[i1 * T_TOK + p1] = warp;
        g_wt [i1 * T_TOK + p1] = s1 * inv;
    }
}

// x -> fp16 hi/lo
__global__ void convx_kernel(const float* __restrict__ x) {
    size_t i = ((size_t)blockIdx.x * 256 + threadIdx.x) * 4;
    float4 v = *(const float4*)(x + i);
    float vv[4] = {v.x, v.y, v.z, v.w};
    __half h[4], l[4];
#pragma unroll
    for (int j = 0; j < 4; j++) {
        h[j] = __float2half_rn(vv[j]);
        l[j] = __float2half_rn(vv[j] - __half2float(h[j]));
    }
    *(uint2*)(g_xhi + i) = *(uint2*)h;
    *(uint2*)(g_xlo + i) = *(uint2*)l;
}

// transpose-convert: src fp32 [K][N] row-major -> dst fp16 [N][K]
__device__ __forceinline__ void transpose_cv(const float* __restrict__ src,
                                             __half* dh, int K, int N) {
    __shared__ float t[32][33];
    int tx = threadIdx.x, ty = threadIdx.y;
    int n0 = blockIdx.x * 32, k0 = blockIdx.y * 32;
#pragma unroll
    for (int i = 0; i < 4; i++)
        t[ty + i * 8][tx] = src[(size_t)(k0 + ty + i * 8) * N + n0 + tx];
    __syncthreads();
#pragma unroll
    for (int i = 0; i < 4; i++) {
        int n = n0 + ty + i * 8, k = k0 + tx;
        dh[(size_t)n * K + k] = __float2half_rn(t[tx][ty + i * 8]);
    }
}

__global__ void convT1_kernel(const float* __restrict__ sg, const float* __restrict__ su,
                              const float* __restrict__ rg, const float* __restrict__ ru) {
    int z = blockIdx.z;
    const float* src; __half* dh; size_t mo;
    if (z == 0)       { src = sg; dh = g_g1h; mo = 0; }
    else if (z == 1)  { src = su; dh = g_u1h; mo = 0; }
    else if (z < 9)   { int e = z - 2; src = rg + (size_t)e * HDIM * IDIM; dh = g_g1h; mo = (size_t)(e + 1) * IDIM * HDIM; }
    else              { int e = z - 9; src = ru + (size_t)e * HDIM * IDIM; dh = g_u1h; mo = (size_t)(e + 1) * IDIM * HDIM; }
    transpose_cv(src, dh + mo, HDIM, IDIM);
}

__global__ void convT2_kernel(const float* __restrict__ sd, const float* __restrict__ rd) {
    int z = blockIdx.z;
    const float* src = (z == 0) ? sd : rd + (size_t)(z - 1) * IDIM * HDIM;
    transpose_cv(src, g_d2h + (size_t)z * HDIM * IDIM, IDIM, HDIM);
}

// ---------------- gemm1: y1 = silu(x@G) * (x@U)  (fp16 x2, A-corrected) ----------------
// CTA tile: 128 m x 64 n (gate and up).  8 warps, warp tile 32m x 32n.
__global__ __launch_bounds__(256, 1)
void gemm1_kernel() {
    extern __shared__ char smem[];
    int tid = threadIdx.x;
    int z = blockIdx.z;
    int nrows; const int* idx;
    if (z == 0) { nrows = T_TOK; idx = nullptr; }
    else        { nrows = g_cnt[z - 1]; idx = g_tok + (z - 1) * T_TOK; }
    int m0 = blockIdx.y * 128;
    if (m0 >= nrows) return;
    int n0 = blockIdx.x * 64;

    const __half* gH = g_g1h + (size_t)z * IDIM * HDIM;
    const __half* uH = g_u1h + (size_t)z * IDIM * HDIM;

    int* arow_s = (int*)(smem + NST * STAGE);
    if (tid < 128) {
        int gm = m0 + tid;
        arow_s[tid] = idx ? ((gm < nrows) ? idx[gm] : idx[0]) : gm;
    }
    __syncthreads();
    uint32_t sb = smem_u32(smem);

    auto load_stage = [&](int s, int k0) {
        uint32_t base = sb + s * STAGE;
#pragma unroll
        for (int i = 0; i < 6; i++) {
            int cid = tid + i * 256;
            int seg = cid >> 9;            // 0 Ahi, 1 Alo, 2 Bhi
            int w2  = cid & 511;
            int row = w2 >> 2, c = w2 & 3;
            const __half* src;
            if (seg < 2) {
                src = ((seg == 0) ? g_xhi : g_xlo) + (size_t)arow_s[row] * HDIM + k0 + c * 8;
            } else {
                const __half* bp;
                if (row < 64) bp = gH + (size_t)(n0 + row) * HDIM;
                else          bp = uH + (size_t)(n0 + row - 64) * HDIM;
                src = bp + k0 + c * 8;
            }
            cp16(base + seg * 10240 + row * PITCHB + c * 16, src);
        }
    };

    int l = tid & 31, w = tid >> 5;
    int wm = w & 3, wn = w >> 2;         // warp grid 4m x 2n
    int mW = wm * 32, nW = wn * 32;
    uint32_t aRow = (uint32_t)(l & 15);
    uint32_t aKb  = (uint32_t)(((l >> 4) & 1) * 16);
    uint32_t bRow = (uint32_t)((l & 7) + ((l >> 4) & 1) * 8);
    uint32_t bKb  = (uint32_t)(((l >> 3) & 1) * 16);

    float Cg[2][4][4] = {}, Cu[2][4][4] = {};

    for (int s = 0; s < NST - 1; s++) { load_stage(s, s * BK); cp_commit(); }
    const int NIT = HDIM / BK;   // 32
    for (int it = 0; it < NIT; it++) {
        cp_wait<NST - 2>();
        __syncthreads();
        uint32_t base = sb + (it % NST) * STAGE;
#pragma unroll
        for (int ks = 0; ks < 2; ks++) {
            int kb = ks * 32;   // bytes (16 elts * 2B)
            uint32_t ah[2][4], al[2][4];
#pragma unroll
            for (int mt = 0; mt < 2; mt++) {
                uint32_t r = base + S_AHI + (mW + mt * 16 + aRow) * PITCHB + kb + aKb;
                ldmx4(ah[mt], r);
                ldmx4(al[mt], r + (S_ALO - S_AHI));
            }
            uint32_t bgh[2][4], buh[2][4];
#pragma unroll
            for (int p = 0; p < 2; p++) {
                uint32_t rg2 = base + S_BHI + (nW + p * 16 + bRow) * PITCHB + kb + bKb;
                ldmx4(bgh[p], rg2);
                ldmx4(buh[p], rg2 + 64 * PITCHB);
            }
#pragma unroll
            for (int mt = 0; mt < 2; mt++)
#pragma unroll
                for (int nt = 0; nt < 4; nt++) {
                    const uint32_t* bG = &bgh[nt >> 1][(nt & 1) * 2];
                    const uint32_t* bU = &buh[nt >> 1][(nt & 1) * 2];
                    mma16816(Cg[mt][nt], ah[mt], bG);
                    mma16816(Cg[mt][nt], al[mt], bG);
                    mma16816(Cu[mt][nt], ah[mt], bU);
                    mma16816(Cu[mt][nt], al[mt], bU);
                }
        }
        int nl = it + NST - 1;
        if (nl < NIT) load_stage(nl % NST, nl * BK);
        cp_commit();
    }

    // epilogue: y = silu(g)*u -> fp16 hi/lo, compacted rows
    size_t zb = (size_t)z * T_TOK;
#pragma unroll
    for (int mt = 0; mt < 2; mt++)
#pragma unroll
        for (int nt = 0; nt < 4; nt++) {
            int mrow = m0 + mW + mt * 16 + (l >> 2);
            int ncol = n0 + nW + nt * 8 + (l & 3) * 2;
#pragma unroll
            for (int h = 0; h < 2; h++) {
                int m = mrow + h * 8;
                if (m < nrows) {
                    float gg0 = Cg[mt][nt][2 * h],     uu0 = Cu[mt][nt][2 * h];
                    float gg1 = Cg[mt][nt][2 * h + 1], uu1 = Cu[mt][nt][2 * h + 1];
                    float y0 = gg0 / (1.f + __expf(-gg0)) * uu0;
                    float y1 = gg1 / (1.f + __expf(-gg1)) * uu1;
                    __half h0 = __float2half_rn(y0), h1 = __float2half_rn(y1);
                    float l0 = y0 - __half2float(h0);
                    float l1 = y1 - __half2float(h1);
                    uint32_t hp; { __half2 t2 = __halves2half2(h0, h1); hp = *(uint32_t*)&t2; }
                    uint32_t lp = pack_h2(l0, l1);
                    size_t off = (zb + m) * IDIM + ncol;
                    *(uint32_t*)(g_y1h + off) = hp;
                    *(uint32_t*)(g_y1l + off) = lp;
                }
            }
        }
}

// ---------------- gemm2: out = y1 @ D ----------------
// CTA tile: 128 m x 128 n.  8 warps, warp tile 64m x 32n (grid 2m x 4n).
__global__ __launch_bounds__(256, 1)
void gemm2_kernel(float* __restrict__ out, int routed) {
    extern __shared__ char smem[];
    int tid = threadIdx.x;
    int z = routed ? (blockIdx.z + 1) : 0;
    int nrows = routed ? g_cnt[z - 1] : T_TOK;
    int m0 = blockIdx.y * 128;
    if (m0 >= nrows) return;
    int n0 = blockIdx.x * 128;

    const __half* aH = g_y1h + (size_t)z * T_TOK * IDIM;
    const __half* aL = g_y1l + (size_t)z * T_TOK * IDIM;
    const __half* bH = g_d2h + (size_t)z * HDIM * IDIM;

    uint32_t sb = smem_u32(smem);

    auto load_stage = [&](int s, int k0) {
        uint32_t base = sb + s * STAGE;
#pragma unroll
        for (int i = 0; i < 6; i++) {
            int cid = tid + i * 256;
            int seg = cid >> 9;
            int w2  = cid & 511;
            int row = w2 >> 2, c = w2 & 3;
            const __half* src;
            if (seg < 2) {
                int r = m0 + row; if (r >= nrows) r = nrows - 1;
                src = ((seg == 0) ? aH : aL) + (size_t)r * IDIM + k0 + c * 8;
            } else {
                src = bH + (size_t)(n0 + row) * IDIM + k0 + c * 8;
            }
            cp16(base + seg * 10240 + row * PITCHB + c * 16, src);
        }
    };

    int l = tid & 31, w = tid >> 5;
    int wm = w & 1, wn = w >> 1;         // warp grid 2m x 4n
    int mW = wm * 64, nW = wn * 32;
    uint32_t aRow = (uint32_t)(l & 15);
    uint32_t aKb  = (uint32_t)(((l >> 4) & 1) * 16);
    uint32_t bRow = (uint32_t)((l & 7) + ((l >> 4) & 1) * 8);
    uint32_t bKb  = (uint32_t)(((l >> 3) & 1) * 16);

    float C[4][4][4] = {};

    for (int s = 0; s < NST - 1; s++) { load_stage(s, s * BK); cp_commit(); }
    const int NIT = IDIM / BK;   // 88
    for (int it = 0; it < NIT; it++) {
        cp_wait<NST - 2>();
        __syncthreads();
        uint32_t base = sb + (it % NST) * STAGE;
#pragma unroll
        for (int ks = 0; ks < 2; ks++) {
            int kb = ks * 32;
            uint32_t ah[4][4], al[4][4];
#pragma unroll
            for (int mt = 0; mt < 4; mt++) {
                uint32_t r = base + S_AHI + (mW + mt * 16 + aRow) * PITCHB + kb + aKb;
                ldmx4(ah[mt], r);
                ldmx4(al[mt], r + (S_ALO - S_AHI));
            }
            uint32_t bh[2][4];
#pragma unroll
            for (int p = 0; p < 2; p++) {
                uint32_t r = base + S_BHI + (nW + p * 16 + bRow) * PITCHB + kb + bKb;
                ldmx4(bh[p], r);
            }
#pragma unroll
            for (int mt = 0; mt < 4; mt++)
#pragma unroll
                for (int nt = 0; nt < 4; nt++) {
                    const uint32_t* bF = &bh[nt >> 1][(nt & 1) * 2];
                    mma16816(C[mt][nt], ah[mt], bF);
                    mma16816(C[mt][nt], al[mt], bF);
                }
        }
        int nl = it + NST - 1;
        if (nl < NIT) load_stage(nl % NST, nl * BK);
        cp_commit();
    }

#pragma unroll
    for (int mt = 0; mt < 4; mt++)
#pragma unroll
        for (int nt = 0; nt < 4; nt++) {
            int mrow = m0 + mW + mt * 16 + (l >> 2);
            int ncol = n0 + nW + nt * 8 + (l & 3) * 2;
#pragma unroll
            for (int h = 0; h < 2; h++) {
                int m = mrow + h * 8;
                if (!routed) {
                    float2 v = make_float2(C[mt][nt][2 * h], C[mt][nt][2 * h + 1]);
                    *(float2*)(out + (size_t)m * HDIM + ncol) = v;
                } else if (m < nrows) {
                    int   tok = g_tok[(z - 1) * T_TOK + m];
                    float wgt = g_wt [(z - 1) * T_TOK + m];
                    float* dst = out + (size_t)tok * HDIM + ncol;
                    atomicAdd(dst,     wgt * C[mt][nt][2 * h]);
                    atomicAdd(dst + 1, wgt * C[mt][nt][2 * h + 1]);
                }
            }
        }
}

// ---------------- launch ----------------
extern "C" void kernel_launch(void* const* d_in, const int* in_sizes, int n_in,
                              void* d_out, int out_size) {
    const float* x    = (const float*)d_in[0];
    const float* wr   = (const float*)d_in[1];
    const float* bias = (const float*)d_in[2];
    const float* sg   = (const float*)d_in[3];
    const float* su   = (const float*)d_in[4];
    const float* sd   = (const float*)d_in[5];
    const float* rg   = (const float*)d_in[6];
    const float* ru   = (const float*)d_in[7];
    const float* rd   = (const float*)d_in[8];
    float* out = (float*)d_out;

    cudaFuncSetAttribute(gemm1_kernel, cudaFuncAttributeMaxDynamicSharedMemorySize, SM_G1);
    cudaFuncSetAttribute(gemm2_kernel, cudaFuncAttributeMaxDynamicSharedMemorySize, SM_G2);

    init_counts_kernel<<<1, 32>>>();
    router_kernel<<<T_TOK / 4, 128>>>(x, wr, bias);
    convx_kernel<<<(T_TOK * HDIM) / 1024, 256>>>(x);
    convT1_kernel<<<dim3(IDIM / 32, HDIM / 32, 16), dim3(32, 8)>>>(sg, su, rg, ru);
    convT2_kernel<<<dim3(HDIM / 32, IDIM / 32, 8), dim3(32, 8)>>>(sd, rd);

    gemm1_kernel<<<dim3(IDIM / 64, T_TOK / 128, 8), 256, SM_G1>>>();
    gemm2_kernel<<<dim3(HDIM / 128, T_TOK / 128, 1), 256, SM_G2>>>(out, 0);
    gemm2_kernel<<<dim3(HDIM / 128, T_TOK / 128, NE), 256, SM_G2>>>(out, 1);
}